// round 9
// baseline (speedup 1.0000x reference)
#include <cuda_runtime.h>
#include <cuda_bf16.h>
#include <math.h>
#include <stdint.h>

#define NN 32768
#define BB 8
#define DEG 9
#define HID 64
#define NMASK (NN - 1)

// Scratch (no allocation allowed in kernel_launch).
__device__ float g_bufA[(size_t)BB * NN * HID];
__device__ float g_bufB[(size_t)BB * NN * HID];
__device__ float g_t1s[(size_t)BB * NN * 8];
__device__ float g_t2s[(size_t)BB * NN * 8];
__device__ uint4 g_wfrag[4][3072];

// ---------------------------------------------------------------------------
// Layer-1 stencil (C=8).
// ---------------------------------------------------------------------------
template <int C, int TR>
__global__ __launch_bounds__(256) void stencil_kernel(
    const float* __restrict__ x, const float* __restrict__ vals,
    float* __restrict__ t1, float* __restrict__ t2)
{
    __shared__ __align__(16) float Xs[(TR + 16) * C];
    __shared__ __align__(16) float T1s[(TR + 8) * C];
    __shared__ float Vs[(TR + 8) * DEG];

    const int b  = blockIdx.y;
    const int r0 = blockIdx.x * TR;
    const int t  = threadIdx.x;
    const float* xb = x + (size_t)b * NN * C;

    for (int idx = t; idx < (TR + 16) * C; idx += 256) {
        int row = idx / C, c = idx % C;
        int g = (r0 - 8 + row + NN) & NMASK;
        Xs[idx] = xb[(size_t)g * C + c];
    }
    for (int idx = t; idx < (TR + 8) * DEG; idx += 256) {
        int row = idx / DEG, j = idx % DEG;
        int g = (r0 - 4 + row + NN) & NMASK;
        Vs[idx] = vals[g * DEG + j];
    }
    __syncthreads();

    for (int idx = t; idx < (TR + 8) * C; idx += 256) {
        int row = idx / C, c = idx % C;
        float s = 0.f;
#pragma unroll
        for (int j = 0; j < DEG; j++) s += Vs[row * DEG + j] * Xs[(row + j) * C + c];
        T1s[idx] = s;
    }
    __syncthreads();

    float* t1b = t1 + (size_t)b * NN * C;
    float* t2b = t2 + (size_t)b * NN * C;
    for (int idx = t; idx < TR * C; idx += 256) {
        int row = idx / C, c = idx % C;
        float s = 0.f;
#pragma unroll
        for (int j = 0; j < DEG; j++) s += Vs[(row + 4) * DEG + j] * T1s[(row + j) * C + c];
        float t2v = 2.f * s - Xs[(row + 8) * C + c];
        size_t o = (size_t)(r0 + row) * C + c;
        t1b[o] = T1s[(row + 4) * C + c];
        t2b[o] = t2v;
    }
}

// ---------------------------------------------------------------------------
// Pack all W matrices -> mma B fragments, one launch.
// ---------------------------------------------------------------------------
__device__ __forceinline__ uint32_t pack_bf16x2(float a, float b) {
    __nv_bfloat162 h = __floats2bfloat162_rn(a, b);
    return *(uint32_t*)&h;
}
__device__ void pack_one(const float* __restrict__ W, int KREAL, int e,
                         uint4* __restrict__ dst)
{
    int l = e & 31, j = (e >> 5) & 7, s = e >> 8;
    int n = j * 8 + (l >> 2);
    int k0 = s * 16 + (l & 3) * 2;
    float w[4];
#pragma unroll
    for (int i = 0; i < 4; i++) {
        int k = k0 + (i >> 1) * 8 + (i & 1);
        w[i] = (k < KREAL) ? W[(size_t)k * 64 + n] : 0.f;
    }
    float h[4], lo[4];
#pragma unroll
    for (int i = 0; i < 4; i++) {
        __nv_bfloat16 hb = __float2bfloat16_rn(w[i]);
        h[i] = __bfloat162float(hb);
        lo[i] = w[i] - h[i];
    }
    dst[e] = make_uint4(pack_bf16x2(h[0], h[1]), pack_bf16x2(h[2], h[3]),
                        pack_bf16x2(lo[0], lo[1]), pack_bf16x2(lo[2], lo[3]));
}
__global__ void pack_all(const float* __restrict__ W1, const float* __restrict__ W2,
                         const float* __restrict__ W3, const float* __restrict__ W4,
                         uint4* __restrict__ wf)
{
    int e = blockIdx.x * blockDim.x + threadIdx.x;
    if (e < 512) { pack_one(W1, 24, e, wf); return; }
    e -= 512;
    if (e < 3072) { pack_one(W2, 192, e, wf + 3072); return; }
    e -= 3072;
    if (e < 3072) { pack_one(W3, 192, e, wf + 2 * 3072); return; }
    e -= 3072;
    if (e < 3072) { pack_one(W4, 192, e, wf + 3 * 3072); return; }
}

// ---------------------------------------------------------------------------
// mma helpers
// ---------------------------------------------------------------------------
__device__ __forceinline__ void mma_bf16(float* c, const uint32_t* a,
                                         uint32_t b0, uint32_t b1) {
    asm volatile(
        "mma.sync.aligned.m16n8k16.row.col.f32.bf16.bf16.f32 "
        "{%0,%1,%2,%3}, {%4,%5,%6,%7}, {%8,%9}, {%0,%1,%2,%3};"
        : "+f"(c[0]), "+f"(c[1]), "+f"(c[2]), "+f"(c[3])
        : "r"(a[0]), "r"(a[1]), "r"(a[2]), "r"(a[3]), "r"(b0), "r"(b1));
}
__device__ __forceinline__ void cvt_hilo(float2 v, uint32_t& hi, uint32_t& lo) {
    __nv_bfloat162 h = __floats2bfloat162_rn(v.x, v.y);
    float2 hf = __bfloat1622float2(h);
    __nv_bfloat162 l = __floats2bfloat162_rn(v.x - hf.x, v.y - hf.y);
    hi = *(uint32_t*)&h;
    lo = *(uint32_t*)&l;
}
// hi bf16 in bits[15:0], lo bf16 in bits[31:16]
__device__ __forceinline__ uint32_t pack_hilo1(float v) {
    __nv_bfloat16 hb = __float2bfloat16_rn(v);
    float hf = __bfloat162float(hb);
    __nv_bfloat16 lb = __float2bfloat16_rn(v - hf);
    return (uint32_t)(*(unsigned short*)&hb) | ((uint32_t)(*(unsigned short*)&lb) << 16);
}
__device__ __forceinline__ float vdot9(const float* __restrict__ vp,
                                       const float* __restrict__ win)
{
    float4 vA = *(const float4*)vp;
    float4 vB = *(const float4*)(vp + 4);
    float  vC = vp[8];
    return vA.x * win[0] + vA.y * win[1] + vA.z * win[2] + vA.w * win[3] +
           vB.x * win[4] + vB.y * win[5] + vB.z * win[6] + vB.w * win[7] +
           vC * win[8];
}

// ---------------------------------------------------------------------------
// Layer-1 GEMM (Fin=8) from gmem (x, t1, t2).
// ---------------------------------------------------------------------------
__device__ __forceinline__ float2 loadA8(const float* __restrict__ s0,
                                         const float* __restrict__ s1,
                                         const float* __restrict__ s2,
                                         size_t row, int k) {
    if (k >= 24) return make_float2(0.f, 0.f);
    const float* sp = (k < 8) ? s0 : (k < 16) ? s1 : s2;
    return *(const float2*)(sp + row * 8 + (k & 7));
}

__global__ __launch_bounds__(256) void mma_gemm8(
    const float* __restrict__ s0, const float* __restrict__ s1,
    const float* __restrict__ s2, const uint4* __restrict__ wf,
    const float* __restrict__ bias, float* __restrict__ out)
{
    const int t = threadIdx.x, warp = t >> 5, l = t & 31;
    const int qr = l >> 2, qc = (l & 3) * 2;
    const size_t mb = (size_t)blockIdx.x * 128 + warp * 16;

    float acc[8][4];
#pragma unroll
    for (int j = 0; j < 8; j++)
#pragma unroll
        for (int i = 0; i < 4; i++) acc[j][i] = 0.f;

#pragma unroll
    for (int s = 0; s < 2; s++) {
        const int k0 = s * 16 + qc;
        float2 v00 = loadA8(s0, s1, s2, mb + qr,     k0);
        float2 v10 = loadA8(s0, s1, s2, mb + qr + 8, k0);
        float2 v01 = loadA8(s0, s1, s2, mb + qr,     k0 + 8);
        float2 v11 = loadA8(s0, s1, s2, mb + qr + 8, k0 + 8);
        uint32_t ahi[4], alo[4];
        cvt_hilo(v00, ahi[0], alo[0]);
        cvt_hilo(v10, ahi[1], alo[1]);
        cvt_hilo(v01, ahi[2], alo[2]);
        cvt_hilo(v11, ahi[3], alo[3]);
#pragma unroll
        for (int j = 0; j < 8; j++) {
            uint4 bfr = __ldg(&wf[(s * 8 + j) * 32 + l]);
            mma_bf16(acc[j], ahi, bfr.x, bfr.y);
            mma_bf16(acc[j], ahi, bfr.z, bfr.w);
            mma_bf16(acc[j], alo, bfr.x, bfr.y);
        }
    }

#pragma unroll
    for (int j = 0; j < 8; j++) {
        const int n = j * 8 + qc;
        float b0 = __ldg(bias + n), b1 = __ldg(bias + n + 1);
        float z[4] = {acc[j][0] + b0, acc[j][1] + b1, acc[j][2] + b0, acc[j][3] + b1};
#pragma unroll
        for (int i = 0; i < 4; i++) z[i] = (z[i] > 0.f) ? z[i] : expm1f(z[i]);
        *(float2*)(out + (mb + qr) * 64 + n)     = make_float2(z[0], z[1]);
        *(float2*)(out + (mb + qr + 8) * 64 + n) = make_float2(z[2], z[3]);
    }
}

// ---------------------------------------------------------------------------
// Fused mid layer v3: stencil + GEMM; T1/T2 stored PRE-SPLIT (bf16 hi|lo u32)
// so the GEMM inner loop does PRMT instead of fp32->bf16 conversion.
// ---------------------------------------------------------------------------
#define SP 66
#define T1R 136
#define T2R 128
#define OFF_T1 0
#define OFF_T2 (T1R * SP)
#define OFF_V  (OFF_T2 + T2R * SP)
#define SM_FLOATS (OFF_V + T1R * 12)
#define SM_MID (SM_FLOATS * 4)
#define OFF_W  SM_FLOATS
#define SM_OUT ((SM_FLOATS + 384) * 4)

// Phase 1: T1 fp32. Phase 2: T2 packed + x read. Phase 2b: T1 -> packed in place.
__device__ __forceinline__ void fused_stencil_v3(
    float* __restrict__ sm, const float* __restrict__ x,
    const float* __restrict__ vals, int b, int r0, int t, bool pack)
{
    const int c = t & 63;
    const int g = t >> 6;

    for (int idx = t; idx < T1R * DEG; idx += 256) {
        int row = idx / DEG, j = idx % DEG;
        int gr = (r0 - 4 + row + NN) & NMASK;
        sm[OFF_V + row * 12 + j] = vals[(size_t)gr * DEG + j];
    }
    __syncthreads();

    const float* xb = x + (size_t)b * NN * 64 + c;

    // Phase 1: T1 rows [r0-4, r0+132), fp32.
    {
        const int tr0 = r0 - 4 + g * 34;
        float xw[9];
#pragma unroll
        for (int j = 0; j < 9; j++)
            xw[j] = __ldg(xb + (size_t)((tr0 - 4 + j + NN) & NMASK) * 64);
#pragma unroll 2
        for (int i = 0; i < 34; i++) {
            const int r = tr0 + i;
            float t1 = vdot9(&sm[OFF_V + (r - r0 + 4) * 12], xw);
            sm[OFF_T1 + (r - r0 + 4) * SP + c] = t1;
            float xn = __ldg(xb + (size_t)((r + 5 + NN) & NMASK) * 64);
#pragma unroll
            for (int j = 0; j < 8; j++) xw[j] = xw[j + 1];
            xw[8] = xn;
        }
    }
    __syncthreads();

    // Phase 2: T2 rows [r0, r0+128) -> packed (or fp32 for fused_out).
#pragma unroll 2
    for (int i = 0; i < 32; i++) {
        const int row = g * 32 + i;
        float s = 0.f;
#pragma unroll
        for (int j = 0; j < DEG; j++)
            s += sm[OFF_V + (row + 4) * 12 + j] * sm[OFF_T1 + (row + j) * SP + c];
        float xv = __ldg(xb + (size_t)(r0 + row) * 64);
        float t2v = 2.f * s - xv;
        if (pack)
            ((uint32_t*)sm)[OFF_T2 + row * SP + c] = pack_hilo1(t2v);
        else
            sm[OFF_T2 + row * SP + c] = t2v;
    }
    __syncthreads();

    if (pack) {
        // Phase 2b: convert T1 in place to packed hi|lo.
        for (int idx = t; idx < T1R * 64; idx += 256) {
            int row = idx >> 6, cc = idx & 63;
            int off = OFF_T1 + row * SP + cc;
            float v = sm[off];
            ((uint32_t*)sm)[off] = pack_hilo1(v);
        }
        __syncthreads();
    }
}

// Fragment from packed plane: two consecutive k -> (hi0,hi1),(lo0,lo1) via PRMT.
__device__ __forceinline__ void frag_packed(const uint32_t* __restrict__ smp,
                                            int off, uint32_t& hi, uint32_t& lo)
{
    uint2 q = *(const uint2*)(smp + off);
    hi = __byte_perm(q.x, q.y, 0x5410);
    lo = __byte_perm(q.x, q.y, 0x7632);
}

__global__ __launch_bounds__(256) void fused_mid(
    const float* __restrict__ x, const float* __restrict__ vals,
    const uint4* __restrict__ wf, const float* __restrict__ bias,
    float* __restrict__ out)
{
    extern __shared__ __align__(16) float sm[];
    const int b  = blockIdx.y;
    const int r0 = blockIdx.x * 128;
    const int t  = threadIdx.x;

    fused_stencil_v3(sm, x, vals, b, r0, t, true);

    const int warp = t >> 5, l = t & 31;
    const int qr = l >> 2, qc = (l & 3) * 2;
    const int rl0 = warp * 16;
    const float* xrow0 = x + ((size_t)b * NN + r0) * 64;
    const uint32_t* smp = (const uint32_t*)sm;

    float acc[8][4];
#pragma unroll
    for (int j = 0; j < 8; j++)
#pragma unroll
        for (int i = 0; i < 4; i++) acc[j][i] = 0.f;

    // s = 0..3 : x segment from gmem (convert in loop)
#pragma unroll
    for (int s = 0; s < 4; s++) {
        const int k0 = s * 16 + qc;
        float2 v00 = *(const float2*)(xrow0 + (size_t)(rl0 + qr) * 64 + k0);
        float2 v10 = *(const float2*)(xrow0 + (size_t)(rl0 + qr + 8) * 64 + k0);
        float2 v01 = *(const float2*)(xrow0 + (size_t)(rl0 + qr) * 64 + k0 + 8);
        float2 v11 = *(const float2*)(xrow0 + (size_t)(rl0 + qr + 8) * 64 + k0 + 8);
        uint32_t ahi[4], alo[4];
        cvt_hilo(v00, ahi[0], alo[0]);
        cvt_hilo(v10, ahi[1], alo[1]);
        cvt_hilo(v01, ahi[2], alo[2]);
        cvt_hilo(v11, ahi[3], alo[3]);
#pragma unroll
        for (int j = 0; j < 8; j++) {
            uint4 bfr = __ldg(&wf[(s * 8 + j) * 32 + l]);
            mma_bf16(acc[j], ahi, bfr.x, bfr.y);
            mma_bf16(acc[j], ahi, bfr.z, bfr.w);
            mma_bf16(acc[j], alo, bfr.x, bfr.y);
        }
    }
    // s = 4..7 : T1 packed plane
#pragma unroll
    for (int s = 4; s < 8; s++) {
        const int k0 = (s - 4) * 16 + qc;
        uint32_t ahi[4], alo[4];
        frag_packed(smp, OFF_T1 + (rl0 + qr + 4) * SP + k0,     ahi[0], alo[0]);
        frag_packed(smp, OFF_T1 + (rl0 + qr + 12) * SP + k0,    ahi[1], alo[1]);
        frag_packed(smp, OFF_T1 + (rl0 + qr + 4) * SP + k0 + 8, ahi[2], alo[2]);
        frag_packed(smp, OFF_T1 + (rl0 + qr + 12) * SP + k0 + 8,ahi[3], alo[3]);
#pragma unroll
        for (int j = 0; j < 8; j++) {
            uint4 bfr = __ldg(&wf[(s * 8 + j) * 32 + l]);
            mma_bf16(acc[j], ahi, bfr.x, bfr.y);
            mma_bf16(acc[j], ahi, bfr.z, bfr.w);
            mma_bf16(acc[j], alo, bfr.x, bfr.y);
        }
    }
    // s = 8..11 : T2 packed plane
#pragma unroll
    for (int s = 8; s < 12; s++) {
        const int k0 = (s - 8) * 16 + qc;
        uint32_t ahi[4], alo[4];
        frag_packed(smp, OFF_T2 + (rl0 + qr) * SP + k0,         ahi[0], alo[0]);
        frag_packed(smp, OFF_T2 + (rl0 + qr + 8) * SP + k0,     ahi[1], alo[1]);
        frag_packed(smp, OFF_T2 + (rl0 + qr) * SP + k0 + 8,     ahi[2], alo[2]);
        frag_packed(smp, OFF_T2 + (rl0 + qr + 8) * SP + k0 + 8, ahi[3], alo[3]);
#pragma unroll
        for (int j = 0; j < 8; j++) {
            uint4 bfr = __ldg(&wf[(s * 8 + j) * 32 + l]);
            mma_bf16(acc[j], ahi, bfr.x, bfr.y);
            mma_bf16(acc[j], ahi, bfr.z, bfr.w);
            mma_bf16(acc[j], alo, bfr.x, bfr.y);
        }
    }

    const size_t mb = (size_t)b * NN + r0 + rl0;
#pragma unroll
    for (int j = 0; j < 8; j++) {
        const int n = j * 8 + qc;
        float b0 = __ldg(bias + n), b1 = __ldg(bias + n + 1);
        float z[4] = {acc[j][0] + b0, acc[j][1] + b1, acc[j][2] + b0, acc[j][3] + b1};
#pragma unroll
        for (int i = 0; i < 4; i++) z[i] = (z[i] > 0.f) ? z[i] : expm1f(z[i]);
        *(float2*)(out + (mb + qr) * 64 + n)     = make_float2(z[0], z[1]);
        *(float2*)(out + (mb + qr + 8) * 64 + n) = make_float2(z[2], z[3]);
    }
}

// ---------------------------------------------------------------------------
// Fused final layer: stencil (fp32, no packing) + 192x2 projection (no ELU).
// ---------------------------------------------------------------------------
__global__ __launch_bounds__(256) void fused_out(
    const float* __restrict__ x, const float* __restrict__ vals,
    const float* __restrict__ W, const float* __restrict__ bias,
    float* __restrict__ out)
{
    extern __shared__ __align__(16) float sm[];
    const int b  = blockIdx.y;
    const int r0 = blockIdx.x * 128;
    const int t  = threadIdx.x;

    for (int idx = t; idx < 384; idx += 256) sm[OFF_W + idx] = W[idx];
    fused_stencil_v3(sm, x, vals, b, r0, t, false);

    if ((t & 1) == 0) {
        const int row = t >> 1;
        const float* xr = x + ((size_t)b * NN + r0 + row) * 64;
        float a0 = bias[0], a1 = bias[1];
#pragma unroll
        for (int i = 0; i < 32; i++) {
            float2 v = *(const float2*)(xr + i * 2);
            const float* wp = sm + OFF_W + (i * 2) * 2;
            a0 += v.x * wp[0] + v.y * wp[2];
            a1 += v.x * wp[1] + v.y * wp[3];
        }
#pragma unroll
        for (int seg = 1; seg < 3; seg++) {
            int base = (seg == 1) ? (OFF_T1 + (row + 4) * SP) : (OFF_T2 + row * SP);
#pragma unroll
            for (int i = 0; i < 32; i++) {
                float2 v = *(const float2*)(sm + base + i * 2);
                const float* wp = sm + OFF_W + (seg * 64 + i * 2) * 2;
                a0 += v.x * wp[0] + v.y * wp[2];
                a1 += v.x * wp[1] + v.y * wp[3];
            }
        }
        *(float2*)&out[((size_t)b * NN + r0 + row) * 2] = make_float2(a0, a1);
    }
}

// ---------------------------------------------------------------------------
extern "C" void kernel_launch(void* const* d_in, const int* in_sizes, int n_in,
                              void* d_out, int out_size)
{
    const float* x    = (const float*)d_in[0];
    const float* vals = (const float*)d_in[3];
    const float* W1 = (const float*)d_in[4];  const float* b1 = (const float*)d_in[5];
    const float* W2 = (const float*)d_in[6];  const float* b2 = (const float*)d_in[7];
    const float* W3 = (const float*)d_in[8];  const float* b3 = (const float*)d_in[9];
    const float* W4 = (const float*)d_in[10]; const float* b4 = (const float*)d_in[11];
    const float* W5 = (const float*)d_in[12]; const float* b5 = (const float*)d_in[13];

    float *bufA, *bufB, *t1, *t2;
    uint4* wf;
    cudaGetSymbolAddress((void**)&bufA, g_bufA);
    cudaGetSymbolAddress((void**)&bufB, g_bufB);
    cudaGetSymbolAddress((void**)&t1,   g_t1s);
    cudaGetSymbolAddress((void**)&t2,   g_t2s);
    cudaGetSymbolAddress((void**)&wf,   g_wfrag);

    cudaFuncSetAttribute(fused_mid, cudaFuncAttributeMaxDynamicSharedMemorySize, SM_MID);
    cudaFuncSetAttribute(fused_out, cudaFuncAttributeMaxDynamicSharedMemorySize, SM_OUT);

    pack_all<<<38, 256>>>(W1, W2, W3, W4, wf);

    const int M = BB * NN;
    dim3 gS8(NN / 256, BB);
    dim3 gF(NN / 128, BB);
    const int gG = M / 128;

    // Layer 1: Fin=8 -> 64
    stencil_kernel<8, 256><<<gS8, 256>>>(x, vals, t1, t2);
    mma_gemm8<<<gG, 256>>>(x, t1, t2, wf, b1, bufA);

    // Layers 2-4: fused stencil+GEMM with pre-split A planes
    fused_mid<<<gF, 256, SM_MID>>>(bufA, vals, wf + 3072, b2, bufB);
    fused_mid<<<gF, 256, SM_MID>>>(bufB, vals, wf + 2 * 3072, b3, bufA);
    fused_mid<<<gF, 256, SM_MID>>>(bufA, vals, wf + 3 * 3072, b4, bufB);

    // Layer 5: fused stencil + 192x2 projection
    fused_out<<<gF, 256, SM_OUT>>>(bufB, vals, W5, b5, (float*)d_out);
}

// round 10
// speedup vs baseline: 1.0229x; 1.0229x over previous
#include <cuda_runtime.h>
#include <cuda_bf16.h>
#include <math.h>
#include <stdint.h>

#define NN 32768
#define BB 8
#define DEG 9
#define HID 64
#define NMASK (NN - 1)

// Scratch (no allocation allowed in kernel_launch).
__device__ float g_bufA[(size_t)BB * NN * HID];
__device__ float g_bufB[(size_t)BB * NN * HID];
__device__ float g_t1s[(size_t)BB * NN * 8];
__device__ float g_t2s[(size_t)BB * NN * 8];
__device__ uint4 g_wfrag[4][3072];

// ---------------------------------------------------------------------------
// Layer-1 stencil (C=8).
// ---------------------------------------------------------------------------
template <int C, int TR>
__global__ __launch_bounds__(256) void stencil_kernel(
    const float* __restrict__ x, const float* __restrict__ vals,
    float* __restrict__ t1, float* __restrict__ t2)
{
    __shared__ __align__(16) float Xs[(TR + 16) * C];
    __shared__ __align__(16) float T1s[(TR + 8) * C];
    __shared__ float Vs[(TR + 8) * DEG];

    const int b  = blockIdx.y;
    const int r0 = blockIdx.x * TR;
    const int t  = threadIdx.x;
    const float* xb = x + (size_t)b * NN * C;

    for (int idx = t; idx < (TR + 16) * C; idx += 256) {
        int row = idx / C, c = idx % C;
        int g = (r0 - 8 + row + NN) & NMASK;
        Xs[idx] = xb[(size_t)g * C + c];
    }
    for (int idx = t; idx < (TR + 8) * DEG; idx += 256) {
        int row = idx / DEG, j = idx % DEG;
        int g = (r0 - 4 + row + NN) & NMASK;
        Vs[idx] = vals[g * DEG + j];
    }
    __syncthreads();

    for (int idx = t; idx < (TR + 8) * C; idx += 256) {
        int row = idx / C, c = idx % C;
        float s = 0.f;
#pragma unroll
        for (int j = 0; j < DEG; j++) s += Vs[row * DEG + j] * Xs[(row + j) * C + c];
        T1s[idx] = s;
    }
    __syncthreads();

    float* t1b = t1 + (size_t)b * NN * C;
    float* t2b = t2 + (size_t)b * NN * C;
    for (int idx = t; idx < TR * C; idx += 256) {
        int row = idx / C, c = idx % C;
        float s = 0.f;
#pragma unroll
        for (int j = 0; j < DEG; j++) s += Vs[(row + 4) * DEG + j] * T1s[(row + j) * C + c];
        float t2v = 2.f * s - Xs[(row + 8) * C + c];
        size_t o = (size_t)(r0 + row) * C + c;
        t1b[o] = T1s[(row + 4) * C + c];
        t2b[o] = t2v;
    }
}

// ---------------------------------------------------------------------------
// Pack all W matrices -> mma B fragments, one launch.
// ---------------------------------------------------------------------------
__device__ __forceinline__ uint32_t pack_bf16x2(float a, float b) {
    __nv_bfloat162 h = __floats2bfloat162_rn(a, b);
    return *(uint32_t*)&h;
}
__device__ void pack_one(const float* __restrict__ W, int KREAL, int e,
                         uint4* __restrict__ dst)
{
    int l = e & 31, j = (e >> 5) & 7, s = e >> 8;
    int n = j * 8 + (l >> 2);
    int k0 = s * 16 + (l & 3) * 2;
    float w[4];
#pragma unroll
    for (int i = 0; i < 4; i++) {
        int k = k0 + (i >> 1) * 8 + (i & 1);
        w[i] = (k < KREAL) ? W[(size_t)k * 64 + n] : 0.f;
    }
    float h[4], lo[4];
#pragma unroll
    for (int i = 0; i < 4; i++) {
        __nv_bfloat16 hb = __float2bfloat16_rn(w[i]);
        h[i] = __bfloat162float(hb);
        lo[i] = w[i] - h[i];
    }
    dst[e] = make_uint4(pack_bf16x2(h[0], h[1]), pack_bf16x2(h[2], h[3]),
                        pack_bf16x2(lo[0], lo[1]), pack_bf16x2(lo[2], lo[3]));
}
__global__ void pack_all(const float* __restrict__ W1, const float* __restrict__ W2,
                         const float* __restrict__ W3, const float* __restrict__ W4,
                         uint4* __restrict__ wf)
{
    int e = blockIdx.x * blockDim.x + threadIdx.x;
    if (e < 512) { pack_one(W1, 24, e, wf); return; }
    e -= 512;
    if (e < 3072) { pack_one(W2, 192, e, wf + 3072); return; }
    e -= 3072;
    if (e < 3072) { pack_one(W3, 192, e, wf + 2 * 3072); return; }
    e -= 3072;
    if (e < 3072) { pack_one(W4, 192, e, wf + 3 * 3072); return; }
}

// ---------------------------------------------------------------------------
// mma helpers
// ---------------------------------------------------------------------------
__device__ __forceinline__ void mma_bf16(float* c, const uint32_t* a,
                                         uint32_t b0, uint32_t b1) {
    asm volatile(
        "mma.sync.aligned.m16n8k16.row.col.f32.bf16.bf16.f32 "
        "{%0,%1,%2,%3}, {%4,%5,%6,%7}, {%8,%9}, {%0,%1,%2,%3};"
        : "+f"(c[0]), "+f"(c[1]), "+f"(c[2]), "+f"(c[3])
        : "r"(a[0]), "r"(a[1]), "r"(a[2]), "r"(a[3]), "r"(b0), "r"(b1));
}
__device__ __forceinline__ void cvt_hilo(float2 v, uint32_t& hi, uint32_t& lo) {
    __nv_bfloat162 h = __floats2bfloat162_rn(v.x, v.y);
    float2 hf = __bfloat1622float2(h);
    __nv_bfloat162 l = __floats2bfloat162_rn(v.x - hf.x, v.y - hf.y);
    hi = *(uint32_t*)&h;
    lo = *(uint32_t*)&l;
}
// hi bf16 in bits[15:0], lo bf16 in bits[31:16]
__device__ __forceinline__ uint32_t pack_hilo1(float v) {
    __nv_bfloat16 hb = __float2bfloat16_rn(v);
    float hf = __bfloat162float(hb);
    __nv_bfloat16 lb = __float2bfloat16_rn(v - hf);
    return (uint32_t)(*(unsigned short*)&hb) | ((uint32_t)(*(unsigned short*)&lb) << 16);
}
__device__ __forceinline__ float unpack_hilo(uint32_t u) {
    __nv_bfloat162 p = *(__nv_bfloat162*)&u;
    float2 f = __bfloat1622float2(p);
    return f.x + f.y;
}
__device__ __forceinline__ float vdot9(const float* __restrict__ vp,
                                       const float* __restrict__ win)
{
    float4 vA = *(const float4*)vp;
    float4 vB = *(const float4*)(vp + 4);
    float  vC = vp[8];
    return vA.x * win[0] + vA.y * win[1] + vA.z * win[2] + vA.w * win[3] +
           vB.x * win[4] + vB.y * win[5] + vB.z * win[6] + vB.w * win[7] +
           vC * win[8];
}

// ---------------------------------------------------------------------------
// Layer-1 GEMM (Fin=8) from gmem (x, t1, t2).
// ---------------------------------------------------------------------------
__device__ __forceinline__ float2 loadA8(const float* __restrict__ s0,
                                         const float* __restrict__ s1,
                                         const float* __restrict__ s2,
                                         size_t row, int k) {
    if (k >= 24) return make_float2(0.f, 0.f);
    const float* sp = (k < 8) ? s0 : (k < 16) ? s1 : s2;
    return *(const float2*)(sp + row * 8 + (k & 7));
}

__global__ __launch_bounds__(256) void mma_gemm8(
    const float* __restrict__ s0, const float* __restrict__ s1,
    const float* __restrict__ s2, const uint4* __restrict__ wf,
    const float* __restrict__ bias, float* __restrict__ out)
{
    const int t = threadIdx.x, warp = t >> 5, l = t & 31;
    const int qr = l >> 2, qc = (l & 3) * 2;
    const size_t mb = (size_t)blockIdx.x * 128 + warp * 16;

    float acc[8][4];
#pragma unroll
    for (int j = 0; j < 8; j++)
#pragma unroll
        for (int i = 0; i < 4; i++) acc[j][i] = 0.f;

#pragma unroll
    for (int s = 0; s < 2; s++) {
        const int k0 = s * 16 + qc;
        float2 v00 = loadA8(s0, s1, s2, mb + qr,     k0);
        float2 v10 = loadA8(s0, s1, s2, mb + qr + 8, k0);
        float2 v01 = loadA8(s0, s1, s2, mb + qr,     k0 + 8);
        float2 v11 = loadA8(s0, s1, s2, mb + qr + 8, k0 + 8);
        uint32_t ahi[4], alo[4];
        cvt_hilo(v00, ahi[0], alo[0]);
        cvt_hilo(v10, ahi[1], alo[1]);
        cvt_hilo(v01, ahi[2], alo[2]);
        cvt_hilo(v11, ahi[3], alo[3]);
#pragma unroll
        for (int j = 0; j < 8; j++) {
            uint4 bfr = __ldg(&wf[(s * 8 + j) * 32 + l]);
            mma_bf16(acc[j], ahi, bfr.x, bfr.y);
            mma_bf16(acc[j], ahi, bfr.z, bfr.w);
            mma_bf16(acc[j], alo, bfr.x, bfr.y);
        }
    }

#pragma unroll
    for (int j = 0; j < 8; j++) {
        const int n = j * 8 + qc;
        float b0 = __ldg(bias + n), b1 = __ldg(bias + n + 1);
        float z[4] = {acc[j][0] + b0, acc[j][1] + b1, acc[j][2] + b0, acc[j][3] + b1};
#pragma unroll
        for (int i = 0; i < 4; i++) z[i] = (z[i] > 0.f) ? z[i] : expm1f(z[i]);
        *(float2*)(out + (mb + qr) * 64 + n)     = make_float2(z[0], z[1]);
        *(float2*)(out + (mb + qr + 8) * 64 + n) = make_float2(z[2], z[3]);
    }
}

// ---------------------------------------------------------------------------
// Fused mid layer v4: stencil (T1 packed at source, sliding-window T2) + GEMM.
// ---------------------------------------------------------------------------
#define SP 66
#define T1R 136
#define T2R 128
#define OFF_T1 0
#define OFF_T2 (T1R * SP)
#define OFF_V  (OFF_T2 + T2R * SP)
#define SM_FLOATS (OFF_V + T1R * 12)
#define SM_MID (SM_FLOATS * 4)
#define OFF_W  SM_FLOATS
#define SM_OUT ((SM_FLOATS + 384) * 4)

template <bool PACK>
__device__ __forceinline__ void fused_stencil_v4(
    float* __restrict__ sm, const float* __restrict__ x,
    const float* __restrict__ vals, int b, int r0, int t)
{
    const int c = t & 63;
    const int g = t >> 6;
    uint32_t* smu = (uint32_t*)sm;

    for (int idx = t; idx < T1R * DEG; idx += 256) {
        int row = idx / DEG, j = idx % DEG;
        int gr = (r0 - 4 + row + NN) & NMASK;
        sm[OFF_V + row * 12 + j] = vals[(size_t)gr * DEG + j];
    }
    __syncthreads();

    const float* xb = x + (size_t)b * NN * 64 + c;

    // Phase 1: T1 rows [r0-4, r0+132); store packed (hi|lo) if PACK.
    {
        const int tr0 = r0 - 4 + g * 34;
        float xw[9];
#pragma unroll
        for (int j = 0; j < 9; j++)
            xw[j] = __ldg(xb + (size_t)((tr0 - 4 + j + NN) & NMASK) * 64);
#pragma unroll 2
        for (int i = 0; i < 34; i++) {
            const int r = tr0 + i;
            float t1 = vdot9(&sm[OFF_V + (r - r0 + 4) * 12], xw);
            int off = OFF_T1 + (r - r0 + 4) * SP + c;
            if (PACK) smu[off] = pack_hilo1(t1);
            else      sm[off]  = t1;
            float xn = __ldg(xb + (size_t)((r + 5 + NN) & NMASK) * 64);
#pragma unroll
            for (int j = 0; j < 8; j++) xw[j] = xw[j + 1];
            xw[8] = xn;
        }
    }
    __syncthreads();

    // Phase 2: T2 rows [r0, r0+128) with a sliding T1 register window
    // (1 LDS per row instead of 9).
    {
        const int row0 = g * 32;
        float w[9];
#pragma unroll
        for (int j = 0; j < 9; j++) {
            int off = OFF_T1 + (row0 + j) * SP + c;
            w[j] = PACK ? unpack_hilo(smu[off]) : sm[off];
        }
#pragma unroll 2
        for (int i = 0; i < 32; i++) {
            const int row = row0 + i;
            float s = vdot9(&sm[OFF_V + (row + 4) * 12], w);
            float xv = __ldg(xb + (size_t)(r0 + row) * 64);
            float t2v = 2.f * s - xv;
            int off2 = OFF_T2 + row * SP + c;
            if (PACK) smu[off2] = pack_hilo1(t2v);
            else      sm[off2]  = t2v;
#pragma unroll
            for (int j = 0; j < 8; j++) w[j] = w[j + 1];
            if (i < 31) {
                int off = OFF_T1 + (row + 9) * SP + c;
                w[8] = PACK ? unpack_hilo(smu[off]) : sm[off];
            }
        }
    }
    __syncthreads();
}

// Fragment from packed plane: two consecutive k -> (hi0,hi1),(lo0,lo1) via PRMT.
__device__ __forceinline__ void frag_packed(const uint32_t* __restrict__ smp,
                                            int off, uint32_t& hi, uint32_t& lo)
{
    uint2 q = *(const uint2*)(smp + off);
    hi = __byte_perm(q.x, q.y, 0x5410);
    lo = __byte_perm(q.x, q.y, 0x7632);
}

__global__ __launch_bounds__(256) void fused_mid(
    const float* __restrict__ x, const float* __restrict__ vals,
    const uint4* __restrict__ wf, const float* __restrict__ bias,
    float* __restrict__ out)
{
    extern __shared__ __align__(16) float sm[];
    const int b  = blockIdx.y;
    const int r0 = blockIdx.x * 128;
    const int t  = threadIdx.x;

    fused_stencil_v4<true>(sm, x, vals, b, r0, t);

    const int warp = t >> 5, l = t & 31;
    const int qr = l >> 2, qc = (l & 3) * 2;
    const int rl0 = warp * 16;
    const float* xrow0 = x + ((size_t)b * NN + r0) * 64;
    const uint32_t* smp = (const uint32_t*)sm;

    float acc[8][4];
#pragma unroll
    for (int j = 0; j < 8; j++)
#pragma unroll
        for (int i = 0; i < 4; i++) acc[j][i] = 0.f;

    // s = 0..3 : x segment from gmem (convert in loop)
#pragma unroll
    for (int s = 0; s < 4; s++) {
        const int k0 = s * 16 + qc;
        float2 v00 = *(const float2*)(xrow0 + (size_t)(rl0 + qr) * 64 + k0);
        float2 v10 = *(const float2*)(xrow0 + (size_t)(rl0 + qr + 8) * 64 + k0);
        float2 v01 = *(const float2*)(xrow0 + (size_t)(rl0 + qr) * 64 + k0 + 8);
        float2 v11 = *(const float2*)(xrow0 + (size_t)(rl0 + qr + 8) * 64 + k0 + 8);
        uint32_t ahi[4], alo[4];
        cvt_hilo(v00, ahi[0], alo[0]);
        cvt_hilo(v10, ahi[1], alo[1]);
        cvt_hilo(v01, ahi[2], alo[2]);
        cvt_hilo(v11, ahi[3], alo[3]);
#pragma unroll
        for (int j = 0; j < 8; j++) {
            uint4 bfr = __ldg(&wf[(s * 8 + j) * 32 + l]);
            mma_bf16(acc[j], ahi, bfr.x, bfr.y);
            mma_bf16(acc[j], ahi, bfr.z, bfr.w);
            mma_bf16(acc[j], alo, bfr.x, bfr.y);
        }
    }
    // s = 4..7 : T1 packed plane
#pragma unroll
    for (int s = 4; s < 8; s++) {
        const int k0 = (s - 4) * 16 + qc;
        uint32_t ahi[4], alo[4];
        frag_packed(smp, OFF_T1 + (rl0 + qr + 4) * SP + k0,     ahi[0], alo[0]);
        frag_packed(smp, OFF_T1 + (rl0 + qr + 12) * SP + k0,    ahi[1], alo[1]);
        frag_packed(smp, OFF_T1 + (rl0 + qr + 4) * SP + k0 + 8, ahi[2], alo[2]);
        frag_packed(smp, OFF_T1 + (rl0 + qr + 12) * SP + k0 + 8,ahi[3], alo[3]);
#pragma unroll
        for (int j = 0; j < 8; j++) {
            uint4 bfr = __ldg(&wf[(s * 8 + j) * 32 + l]);
            mma_bf16(acc[j], ahi, bfr.x, bfr.y);
            mma_bf16(acc[j], ahi, bfr.z, bfr.w);
            mma_bf16(acc[j], alo, bfr.x, bfr.y);
        }
    }
    // s = 8..11 : T2 packed plane
#pragma unroll
    for (int s = 8; s < 12; s++) {
        const int k0 = (s - 8) * 16 + qc;
        uint32_t ahi[4], alo[4];
        frag_packed(smp, OFF_T2 + (rl0 + qr) * SP + k0,         ahi[0], alo[0]);
        frag_packed(smp, OFF_T2 + (rl0 + qr + 8) * SP + k0,     ahi[1], alo[1]);
        frag_packed(smp, OFF_T2 + (rl0 + qr) * SP + k0 + 8,     ahi[2], alo[2]);
        frag_packed(smp, OFF_T2 + (rl0 + qr + 8) * SP + k0 + 8, ahi[3], alo[3]);
#pragma unroll
        for (int j = 0; j < 8; j++) {
            uint4 bfr = __ldg(&wf[(s * 8 + j) * 32 + l]);
            mma_bf16(acc[j], ahi, bfr.x, bfr.y);
            mma_bf16(acc[j], ahi, bfr.z, bfr.w);
            mma_bf16(acc[j], alo, bfr.x, bfr.y);
        }
    }

    const size_t mb = (size_t)b * NN + r0 + rl0;
#pragma unroll
    for (int j = 0; j < 8; j++) {
        const int n = j * 8 + qc;
        float b0 = __ldg(bias + n), b1 = __ldg(bias + n + 1);
        float z[4] = {acc[j][0] + b0, acc[j][1] + b1, acc[j][2] + b0, acc[j][3] + b1};
#pragma unroll
        for (int i = 0; i < 4; i++) z[i] = (z[i] > 0.f) ? z[i] : expm1f(z[i]);
        *(float2*)(out + (mb + qr) * 64 + n)     = make_float2(z[0], z[1]);
        *(float2*)(out + (mb + qr + 8) * 64 + n) = make_float2(z[2], z[3]);
    }
}

// ---------------------------------------------------------------------------
// Fused final layer: stencil (fp32 planes) + 192x2 projection (no ELU).
// ---------------------------------------------------------------------------
__global__ __launch_bounds__(256) void fused_out(
    const float* __restrict__ x, const float* __restrict__ vals,
    const float* __restrict__ W, const float* __restrict__ bias,
    float* __restrict__ out)
{
    extern __shared__ __align__(16) float sm[];
    const int b  = blockIdx.y;
    const int r0 = blockIdx.x * 128;
    const int t  = threadIdx.x;

    for (int idx = t; idx < 384; idx += 256) sm[OFF_W + idx] = W[idx];
    fused_stencil_v4<false>(sm, x, vals, b, r0, t);

    if ((t & 1) == 0) {
        const int row = t >> 1;
        const float* xr = x + ((size_t)b * NN + r0 + row) * 64;
        float a0 = bias[0], a1 = bias[1];
#pragma unroll
        for (int i = 0; i < 32; i++) {
            float2 v = *(const float2*)(xr + i * 2);
            const float* wp = sm + OFF_W + (i * 2) * 2;
            a0 += v.x * wp[0] + v.y * wp[2];
            a1 += v.x * wp[1] + v.y * wp[3];
        }
#pragma unroll
        for (int seg = 1; seg < 3; seg++) {
            int base = (seg == 1) ? (OFF_T1 + (row + 4) * SP) : (OFF_T2 + row * SP);
#pragma unroll
            for (int i = 0; i < 32; i++) {
                float2 v = *(const float2*)(sm + base + i * 2);
                const float* wp = sm + OFF_W + (seg * 64 + i * 2) * 2;
                a0 += v.x * wp[0] + v.y * wp[2];
                a1 += v.x * wp[1] + v.y * wp[3];
            }
        }
        *(float2*)&out[((size_t)b * NN + r0 + row) * 2] = make_float2(a0, a1);
    }
}

// ---------------------------------------------------------------------------
extern "C" void kernel_launch(void* const* d_in, const int* in_sizes, int n_in,
                              void* d_out, int out_size)
{
    const float* x    = (const float*)d_in[0];
    const float* vals = (const float*)d_in[3];
    const float* W1 = (const float*)d_in[4];  const float* b1 = (const float*)d_in[5];
    const float* W2 = (const float*)d_in[6];  const float* b2 = (const float*)d_in[7];
    const float* W3 = (const float*)d_in[8];  const float* b3 = (const float*)d_in[9];
    const float* W4 = (const float*)d_in[10]; const float* b4 = (const float*)d_in[11];
    const float* W5 = (const float*)d_in[12]; const float* b5 = (const float*)d_in[13];

    float *bufA, *bufB, *t1, *t2;
    uint4* wf;
    cudaGetSymbolAddress((void**)&bufA, g_bufA);
    cudaGetSymbolAddress((void**)&bufB, g_bufB);
    cudaGetSymbolAddress((void**)&t1,   g_t1s);
    cudaGetSymbolAddress((void**)&t2,   g_t2s);
    cudaGetSymbolAddress((void**)&wf,   g_wfrag);

    cudaFuncSetAttribute(fused_mid, cudaFuncAttributeMaxDynamicSharedMemorySize, SM_MID);
    cudaFuncSetAttribute(fused_out, cudaFuncAttributeMaxDynamicSharedMemorySize, SM_OUT);

    pack_all<<<38, 256>>>(W1, W2, W3, W4, wf);

    const int M = BB * NN;
    dim3 gS8(NN / 256, BB);
    dim3 gF(NN / 128, BB);
    const int gG = M / 128;

    // Layer 1: Fin=8 -> 64
    stencil_kernel<8, 256><<<gS8, 256>>>(x, vals, t1, t2);
    mma_gemm8<<<gG, 256>>>(x, t1, t2, wf, b1, bufA);

    // Layers 2-4: fused stencil+GEMM
    fused_mid<<<gF, 256, SM_MID>>>(bufA, vals, wf + 3072, b2, bufB);
    fused_mid<<<gF, 256, SM_MID>>>(bufB, vals, wf + 2 * 3072, b3, bufA);
    fused_mid<<<gF, 256, SM_MID>>>(bufA, vals, wf + 3 * 3072, b4, bufB);

    // Layer 5: fused stencil + 192x2 projection
    fused_out<<<gF, 256, SM_OUT>>>(bufB, vals, W5, b5, (float*)d_out);
}

// round 12
// speedup vs baseline: 1.1780x; 1.1516x over previous
#include <cuda_runtime.h>
#include <cuda_bf16.h>
#include <math.h>
#include <stdint.h>

#define NN 32768
#define BB 8
#define DEG 9
#define HID 64
#define NMASK (NN - 1)

// Scratch (no allocation allowed in kernel_launch).
__device__ float g_bufA[(size_t)BB * NN * HID];
__device__ float g_bufB[(size_t)BB * NN * HID];
__device__ float g_t1s[(size_t)BB * NN * 8];
__device__ float g_t2s[(size_t)BB * NN * 8];
__device__ uint4 g_wfrag[4][3072];

// ---------------------------------------------------------------------------
// Layer-1 stencil (C=8).
// ---------------------------------------------------------------------------
template <int C, int TR>
__global__ __launch_bounds__(256) void stencil_kernel(
    const float* __restrict__ x, const float* __restrict__ vals,
    float* __restrict__ t1, float* __restrict__ t2)
{
    __shared__ __align__(16) float Xs[(TR + 16) * C];
    __shared__ __align__(16) float T1s[(TR + 8) * C];
    __shared__ float Vs[(TR + 8) * DEG];

    const int b  = blockIdx.y;
    const int r0 = blockIdx.x * TR;
    const int t  = threadIdx.x;
    const float* xb = x + (size_t)b * NN * C;

    for (int idx = t; idx < (TR + 16) * C; idx += 256) {
        int row = idx / C, c = idx % C;
        int g = (r0 - 8 + row + NN) & NMASK;
        Xs[idx] = xb[(size_t)g * C + c];
    }
    for (int idx = t; idx < (TR + 8) * DEG; idx += 256) {
        int row = idx / DEG, j = idx % DEG;
        int g = (r0 - 4 + row + NN) & NMASK;
        Vs[idx] = vals[g * DEG + j];
    }
    __syncthreads();

    for (int idx = t; idx < (TR + 8) * C; idx += 256) {
        int row = idx / C, c = idx % C;
        float s = 0.f;
#pragma unroll
        for (int j = 0; j < DEG; j++) s += Vs[row * DEG + j] * Xs[(row + j) * C + c];
        T1s[idx] = s;
    }
    __syncthreads();

    float* t1b = t1 + (size_t)b * NN * C;
    float* t2b = t2 + (size_t)b * NN * C;
    for (int idx = t; idx < TR * C; idx += 256) {
        int row = idx / C, c = idx % C;
        float s = 0.f;
#pragma unroll
        for (int j = 0; j < DEG; j++) s += Vs[(row + 4) * DEG + j] * T1s[(row + j) * C + c];
        float t2v = 2.f * s - Xs[(row + 8) * C + c];
        size_t o = (size_t)(r0 + row) * C + c;
        t1b[o] = T1s[(row + 4) * C + c];
        t2b[o] = t2v;
    }
}

// ---------------------------------------------------------------------------
// Pack all W matrices -> mma B fragments, one launch.
// ---------------------------------------------------------------------------
__device__ __forceinline__ uint32_t pack_bf16x2(float a, float b) {
    __nv_bfloat162 h = __floats2bfloat162_rn(a, b);
    return *(uint32_t*)&h;
}
__device__ void pack_one(const float* __restrict__ W, int KREAL, int e,
                         uint4* __restrict__ dst)
{
    int l = e & 31, j = (e >> 5) & 7, s = e >> 8;
    int n = j * 8 + (l >> 2);
    int k0 = s * 16 + (l & 3) * 2;
    float w[4];
#pragma unroll
    for (int i = 0; i < 4; i++) {
        int k = k0 + (i >> 1) * 8 + (i & 1);
        w[i] = (k < KREAL) ? W[(size_t)k * 64 + n] : 0.f;
    }
    float h[4], lo[4];
#pragma unroll
    for (int i = 0; i < 4; i++) {
        __nv_bfloat16 hb = __float2bfloat16_rn(w[i]);
        h[i] = __bfloat162float(hb);
        lo[i] = w[i] - h[i];
    }
    dst[e] = make_uint4(pack_bf16x2(h[0], h[1]), pack_bf16x2(h[2], h[3]),
                        pack_bf16x2(lo[0], lo[1]), pack_bf16x2(lo[2], lo[3]));
}
__global__ void pack_all(const float* __restrict__ W1, const float* __restrict__ W2,
                         const float* __restrict__ W3, const float* __restrict__ W4,
                         uint4* __restrict__ wf)
{
    int e = blockIdx.x * blockDim.x + threadIdx.x;
    if (e < 512) { pack_one(W1, 24, e, wf); return; }
    e -= 512;
    if (e < 3072) { pack_one(W2, 192, e, wf + 3072); return; }
    e -= 3072;
    if (e < 3072) { pack_one(W3, 192, e, wf + 2 * 3072); return; }
    e -= 3072;
    if (e < 3072) { pack_one(W4, 192, e, wf + 3 * 3072); return; }
}

// ---------------------------------------------------------------------------
// mma helpers
// ---------------------------------------------------------------------------
__device__ __forceinline__ void mma_bf16(float* c, const uint32_t* a,
                                         uint32_t b0, uint32_t b1) {
    asm volatile(
        "mma.sync.aligned.m16n8k16.row.col.f32.bf16.bf16.f32 "
        "{%0,%1,%2,%3}, {%4,%5,%6,%7}, {%8,%9}, {%0,%1,%2,%3};"
        : "+f"(c[0]), "+f"(c[1]), "+f"(c[2]), "+f"(c[3])
        : "r"(a[0]), "r"(a[1]), "r"(a[2]), "r"(a[3]), "r"(b0), "r"(b1));
}
__device__ __forceinline__ void cvt_hilo(float2 v, uint32_t& hi, uint32_t& lo) {
    __nv_bfloat162 h = __floats2bfloat162_rn(v.x, v.y);
    float2 hf = __bfloat1622float2(h);
    __nv_bfloat162 l = __floats2bfloat162_rn(v.x - hf.x, v.y - hf.y);
    hi = *(uint32_t*)&h;
    lo = *(uint32_t*)&l;
}
// 9-tap dot for 4 channels at once.
__device__ __forceinline__ float4 vdot9x4(const float* __restrict__ vp,
                                          const float4* __restrict__ win)
{
    float4 vA = *(const float4*)vp;
    float4 vB = *(const float4*)(vp + 4);
    float  vC = vp[8];
    float v[9] = {vA.x, vA.y, vA.z, vA.w, vB.x, vB.y, vB.z, vB.w, vC};
    float4 s = make_float4(0.f, 0.f, 0.f, 0.f);
#pragma unroll
    for (int j = 0; j < 9; j++) {
        s.x += v[j] * win[j].x;
        s.y += v[j] * win[j].y;
        s.z += v[j] * win[j].z;
        s.w += v[j] * win[j].w;
    }
    return s;
}

// ---------------------------------------------------------------------------
// Layer-1 GEMM (Fin=8) from gmem (x, t1, t2).
// ---------------------------------------------------------------------------
__device__ __forceinline__ float2 loadA8(const float* __restrict__ s0,
                                         const float* __restrict__ s1,
                                         const float* __restrict__ s2,
                                         size_t row, int k) {
    if (k >= 24) return make_float2(0.f, 0.f);
    const float* sp = (k < 8) ? s0 : (k < 16) ? s1 : s2;
    return *(const float2*)(sp + row * 8 + (k & 7));
}

__global__ __launch_bounds__(256) void mma_gemm8(
    const float* __restrict__ s0, const float* __restrict__ s1,
    const float* __restrict__ s2, const uint4* __restrict__ wf,
    const float* __restrict__ bias, float* __restrict__ out)
{
    const int t = threadIdx.x, warp = t >> 5, l = t & 31;
    const int qr = l >> 2, qc = (l & 3) * 2;
    const size_t mb = (size_t)blockIdx.x * 128 + warp * 16;

    float acc[8][4];
#pragma unroll
    for (int j = 0; j < 8; j++)
#pragma unroll
        for (int i = 0; i < 4; i++) acc[j][i] = 0.f;

#pragma unroll
    for (int s = 0; s < 2; s++) {
        const int k0 = s * 16 + qc;
        float2 v00 = loadA8(s0, s1, s2, mb + qr,     k0);
        float2 v10 = loadA8(s0, s1, s2, mb + qr + 8, k0);
        float2 v01 = loadA8(s0, s1, s2, mb + qr,     k0 + 8);
        float2 v11 = loadA8(s0, s1, s2, mb + qr + 8, k0 + 8);
        uint32_t ahi[4], alo[4];
        cvt_hilo(v00, ahi[0], alo[0]);
        cvt_hilo(v10, ahi[1], alo[1]);
        cvt_hilo(v01, ahi[2], alo[2]);
        cvt_hilo(v11, ahi[3], alo[3]);
#pragma unroll
        for (int j = 0; j < 8; j++) {
            uint4 bfr = __ldg(&wf[(s * 8 + j) * 32 + l]);
            mma_bf16(acc[j], ahi, bfr.x, bfr.y);
            mma_bf16(acc[j], ahi, bfr.z, bfr.w);
            mma_bf16(acc[j], alo, bfr.x, bfr.y);
        }
    }

#pragma unroll
    for (int j = 0; j < 8; j++) {
        const int n = j * 8 + qc;
        float b0 = __ldg(bias + n), b1 = __ldg(bias + n + 1);
        float z[4] = {acc[j][0] + b0, acc[j][1] + b1, acc[j][2] + b0, acc[j][3] + b1};
#pragma unroll
        for (int i = 0; i < 4; i++) z[i] = (z[i] > 0.f) ? z[i] : expm1f(z[i]);
        *(float2*)(out + (mb + qr) * 64 + n)     = make_float2(z[0], z[1]);
        *(float2*)(out + (mb + qr + 8) * 64 + n) = make_float2(z[2], z[3]);
    }
}

// ---------------------------------------------------------------------------
// Fused mid layer v5: float4-vectorized stencil + mma GEMM (fp32 planes).
// 256 threads = 16 col-threads (x4 ch) x 16 row-groups.
// T1 plane stride 68 (float4-aligned), T2 stride 66.
// ---------------------------------------------------------------------------
#define SPT1 68
#define SPT2 66
#define T1R 136
#define T2R 128
#define OFF_T1 0
#define OFF_T2 (T1R * SPT1)                  // 9248
#define OFF_V  (OFF_T2 + T2R * SPT2)         // 17696 (16B aligned)
#define SM_FLOATS (OFF_V + T1R * 12)         // 19328
#define SM_MID (SM_FLOATS * 4)               // 77312 B -> 3 CTAs/SM
#define OFF_W  SM_FLOATS
#define SM_OUT ((SM_FLOATS + 384) * 4)

__device__ __forceinline__ void fused_stencil_v5(
    float* __restrict__ sm, const float* __restrict__ x,
    const float* __restrict__ vals, int b, int r0, int t)
{
    const int c4  = (t & 15) * 4;   // first of 4 owned channels
    const int grp = t >> 4;         // 0..15

    // vals rows [r0-4, r0+132) -> V plane stride 12
    for (int idx = t; idx < T1R * DEG; idx += 256) {
        int row = idx / DEG, j = idx % DEG;
        int gr = (r0 - 4 + row + NN) & NMASK;
        sm[OFF_V + row * 12 + j] = vals[(size_t)gr * DEG + j];
    }
    __syncthreads();

    const float4* xb4 = (const float4*)(x + (size_t)b * NN * 64) + (c4 >> 2);

    // Phase 1: T1 local rows [grp*9, grp*9+9) clipped to [0,136).
    {
        const int lr0 = grp * 9;
        float4 xw[9];
#pragma unroll
        for (int j = 0; j < 9; j++) {
            int gr = (r0 - 8 + lr0 + j + NN) & NMASK;
            xw[j] = __ldg(xb4 + (size_t)gr * 16);
        }
#pragma unroll
        for (int i = 0; i < 9; i++) {
            const int lr = lr0 + i;
            if (lr < T1R) {
                float4 s = vdot9x4(&sm[OFF_V + lr * 12], xw);
                *(float4*)&sm[OFF_T1 + lr * SPT1 + c4] = s;
            }
            if (i < 8) {
                int gr = (r0 - 8 + lr0 + 9 + i + NN) & NMASK;
                float4 xn = __ldg(xb4 + (size_t)gr * 16);
#pragma unroll
                for (int j = 0; j < 8; j++) xw[j] = xw[j + 1];
                xw[8] = xn;
            }
        }
    }
    __syncthreads();

    // Phase 2: T2 rows [grp*8, grp*8+8), sliding T1 window (float4).
    {
        const int row0 = grp * 8;
        float4 w[9];
#pragma unroll
        for (int j = 0; j < 9; j++)
            w[j] = *(const float4*)&sm[OFF_T1 + (row0 + j) * SPT1 + c4];
#pragma unroll
        for (int i = 0; i < 8; i++) {
            const int row = row0 + i;
            float4 s = vdot9x4(&sm[OFF_V + (row + 4) * 12], w);
            float4 xv = __ldg(xb4 + (size_t)(r0 + row) * 16);
            float4 t2;
            t2.x = 2.f * s.x - xv.x;
            t2.y = 2.f * s.y - xv.y;
            t2.z = 2.f * s.z - xv.z;
            t2.w = 2.f * s.w - xv.w;
            // T2 stride 66: two float2 stores (8B-aligned)
            *(float2*)&sm[OFF_T2 + row * SPT2 + c4]     = make_float2(t2.x, t2.y);
            *(float2*)&sm[OFF_T2 + row * SPT2 + c4 + 2] = make_float2(t2.z, t2.w);
            if (i < 7) {
#pragma unroll
                for (int j = 0; j < 8; j++) w[j] = w[j + 1];
                w[8] = *(const float4*)&sm[OFF_T1 + (row + 9) * SPT1 + c4];
            }
        }
    }
    __syncthreads();
}

__device__ __forceinline__ float2 loadA_f(const float* __restrict__ sm,
                                          const float* __restrict__ xrow0,
                                          int rl, int k)
{
    if (k < 64)  return *(const float2*)(xrow0 + (size_t)rl * 64 + k);
    if (k < 128) return *(const float2*)(sm + OFF_T1 + (rl + 4) * SPT1 + (k - 64));
    return *(const float2*)(sm + OFF_T2 + rl * SPT2 + (k - 128));
}

__global__ __launch_bounds__(256, 3) void fused_mid(
    const float* __restrict__ x, const float* __restrict__ vals,
    const uint4* __restrict__ wf, const float* __restrict__ bias,
    float* __restrict__ out)
{
    extern __shared__ __align__(16) float sm[];
    const int b  = blockIdx.y;
    const int r0 = blockIdx.x * 128;
    const int t  = threadIdx.x;

    fused_stencil_v5(sm, x, vals, b, r0, t);

    const int warp = t >> 5, l = t & 31;
    const int qr = l >> 2, qc = (l & 3) * 2;
    const int rl0 = warp * 16;
    const float* xrow0 = x + ((size_t)b * NN + r0) * 64;

    float acc[8][4];
#pragma unroll
    for (int j = 0; j < 8; j++)
#pragma unroll
        for (int i = 0; i < 4; i++) acc[j][i] = 0.f;

#pragma unroll
    for (int s = 0; s < 12; s++) {
        const int k0 = s * 16 + qc;
        float2 v00 = loadA_f(sm, xrow0, rl0 + qr,     k0);
        float2 v10 = loadA_f(sm, xrow0, rl0 + qr + 8, k0);
        float2 v01 = loadA_f(sm, xrow0, rl0 + qr,     k0 + 8);
        float2 v11 = loadA_f(sm, xrow0, rl0 + qr + 8, k0 + 8);
        uint32_t ahi[4], alo[4];
        cvt_hilo(v00, ahi[0], alo[0]);
        cvt_hilo(v10, ahi[1], alo[1]);
        cvt_hilo(v01, ahi[2], alo[2]);
        cvt_hilo(v11, ahi[3], alo[3]);
#pragma unroll
        for (int j = 0; j < 8; j++) {
            uint4 bfr = __ldg(&wf[(s * 8 + j) * 32 + l]);
            mma_bf16(acc[j], ahi, bfr.x, bfr.y);
            mma_bf16(acc[j], ahi, bfr.z, bfr.w);
            mma_bf16(acc[j], alo, bfr.x, bfr.y);
        }
    }

    const size_t mb = (size_t)b * NN + r0 + rl0;
#pragma unroll
    for (int j = 0; j < 8; j++) {
        const int n = j * 8 + qc;
        float b0 = __ldg(bias + n), b1 = __ldg(bias + n + 1);
        float z[4] = {acc[j][0] + b0, acc[j][1] + b1, acc[j][2] + b0, acc[j][3] + b1};
#pragma unroll
        for (int i = 0; i < 4; i++) z[i] = (z[i] > 0.f) ? z[i] : expm1f(z[i]);
        *(float2*)(out + (mb + qr) * 64 + n)     = make_float2(z[0], z[1]);
        *(float2*)(out + (mb + qr + 8) * 64 + n) = make_float2(z[2], z[3]);
    }
}

// ---------------------------------------------------------------------------
// Fused final layer: vectorized stencil + 192x2 projection (no ELU).
// ---------------------------------------------------------------------------
__global__ __launch_bounds__(256, 3) void fused_out(
    const float* __restrict__ x, const float* __restrict__ vals,
    const float* __restrict__ W, const float* __restrict__ bias,
    float* __restrict__ out)
{
    extern __shared__ __align__(16) float sm[];
    const int b  = blockIdx.y;
    const int r0 = blockIdx.x * 128;
    const int t  = threadIdx.x;

    for (int idx = t; idx < 384; idx += 256) sm[OFF_W + idx] = W[idx];
    fused_stencil_v5(sm, x, vals, b, r0, t);

    if ((t & 1) == 0) {
        const int row = t >> 1;
        const float* xr = x + ((size_t)b * NN + r0 + row) * 64;
        float a0 = bias[0], a1 = bias[1];
#pragma unroll
        for (int i = 0; i < 32; i++) {
            float2 v = *(const float2*)(xr + i * 2);
            const float* wp = sm + OFF_W + (i * 2) * 2;
            a0 += v.x * wp[0] + v.y * wp[2];
            a1 += v.x * wp[1] + v.y * wp[3];
        }
        {
            const float* base = sm + OFF_T1 + (row + 4) * SPT1;
#pragma unroll
            for (int i = 0; i < 32; i++) {
                float2 v = *(const float2*)(base + i * 2);
                const float* wp = sm + OFF_W + (64 + i * 2) * 2;
                a0 += v.x * wp[0] + v.y * wp[2];
                a1 += v.x * wp[1] + v.y * wp[3];
            }
        }
        {
            const float* base = sm + OFF_T2 + row * SPT2;
#pragma unroll
            for (int i = 0; i < 32; i++) {
                float2 v = *(const float2*)(base + i * 2);
                const float* wp = sm + OFF_W + (128 + i * 2) * 2;
                a0 += v.x * wp[0] + v.y * wp[2];
                a1 += v.x * wp[1] + v.y * wp[3];
            }
        }
        *(float2*)&out[((size_t)b * NN + r0 + row) * 2] = make_float2(a0, a1);
    }
}

// ---------------------------------------------------------------------------
extern "C" void kernel_launch(void* const* d_in, const int* in_sizes, int n_in,
                              void* d_out, int out_size)
{
    const float* x    = (const float*)d_in[0];
    const float* vals = (const float*)d_in[3];
    const float* W1 = (const float*)d_in[4];  const float* b1 = (const float*)d_in[5];
    const float* W2 = (const float*)d_in[6];  const float* b2 = (const float*)d_in[7];
    const float* W3 = (const float*)d_in[8];  const float* b3 = (const float*)d_in[9];
    const float* W4 = (const float*)d_in[10]; const float* b4 = (const float*)d_in[11];
    const float* W5 = (const float*)d_in[12]; const float* b5 = (const float*)d_in[13];

    float *bufA, *bufB, *t1, *t2;
    uint4* wf;
    cudaGetSymbolAddress((void**)&bufA, g_bufA);
    cudaGetSymbolAddress((void**)&bufB, g_bufB);
    cudaGetSymbolAddress((void**)&t1,   g_t1s);
    cudaGetSymbolAddress((void**)&t2,   g_t2s);
    cudaGetSymbolAddress((void**)&wf,   g_wfrag);

    cudaFuncSetAttribute(fused_mid, cudaFuncAttributeMaxDynamicSharedMemorySize, SM_MID);
    cudaFuncSetAttribute(fused_out, cudaFuncAttributeMaxDynamicSharedMemorySize, SM_OUT);

    pack_all<<<38, 256>>>(W1, W2, W3, W4, wf);

    const int M = BB * NN;
    dim3 gS8(NN / 256, BB);
    dim3 gF(NN / 128, BB);
    const int gG = M / 128;

    // Layer 1: Fin=8 -> 64
    stencil_kernel<8, 256><<<gS8, 256>>>(x, vals, t1, t2);
    mma_gemm8<<<gG, 256>>>(x, t1, t2, wf, b1, bufA);

    // Layers 2-4: fused vectorized stencil + GEMM
    fused_mid<<<gF, 256, SM_MID>>>(bufA, vals, wf + 3072, b2, bufB);
    fused_mid<<<gF, 256, SM_MID>>>(bufB, vals, wf + 2 * 3072, b3, bufA);
    fused_mid<<<gF, 256, SM_MID>>>(bufA, vals, wf + 3 * 3072, b4, bufB);

    // Layer 5: fused stencil + 192x2 projection
    fused_out<<<gF, 256, SM_OUT>>>(bufB, vals, W5, b5, (float*)d_out);
}

// round 13
// speedup vs baseline: 1.2203x; 1.0360x over previous
#include <cuda_runtime.h>
#include <cuda_bf16.h>
#include <math.h>
#include <stdint.h>

#define NN 32768
#define BB 8
#define DEG 9
#define HID 64
#define NMASK (NN - 1)

// Scratch (no allocation allowed in kernel_launch).
__device__ float g_bufA[(size_t)BB * NN * HID];
__device__ float g_bufB[(size_t)BB * NN * HID];
__device__ float g_t1s[(size_t)BB * NN * 8];
__device__ float g_t2s[(size_t)BB * NN * 8];
__device__ uint4 g_wfrag[4][3072];

// ---------------------------------------------------------------------------
// Layer-1 stencil (C=8).
// ---------------------------------------------------------------------------
template <int C, int TR>
__global__ __launch_bounds__(256) void stencil_kernel(
    const float* __restrict__ x, const float* __restrict__ vals,
    float* __restrict__ t1, float* __restrict__ t2)
{
    __shared__ __align__(16) float Xs[(TR + 16) * C];
    __shared__ __align__(16) float T1s[(TR + 8) * C];
    __shared__ float Vs[(TR + 8) * DEG];

    const int b  = blockIdx.y;
    const int r0 = blockIdx.x * TR;
    const int t  = threadIdx.x;
    const float* xb = x + (size_t)b * NN * C;

    for (int idx = t; idx < (TR + 16) * C; idx += 256) {
        int row = idx / C, c = idx % C;
        int g = (r0 - 8 + row + NN) & NMASK;
        Xs[idx] = xb[(size_t)g * C + c];
    }
    for (int idx = t; idx < (TR + 8) * DEG; idx += 256) {
        int row = idx / DEG, j = idx % DEG;
        int g = (r0 - 4 + row + NN) & NMASK;
        Vs[idx] = vals[g * DEG + j];
    }
    __syncthreads();

    for (int idx = t; idx < (TR + 8) * C; idx += 256) {
        int row = idx / C, c = idx % C;
        float s = 0.f;
#pragma unroll
        for (int j = 0; j < DEG; j++) s += Vs[row * DEG + j] * Xs[(row + j) * C + c];
        T1s[idx] = s;
    }
    __syncthreads();

    float* t1b = t1 + (size_t)b * NN * C;
    float* t2b = t2 + (size_t)b * NN * C;
    for (int idx = t; idx < TR * C; idx += 256) {
        int row = idx / C, c = idx % C;
        float s = 0.f;
#pragma unroll
        for (int j = 0; j < DEG; j++) s += Vs[(row + 4) * DEG + j] * T1s[(row + j) * C + c];
        float t2v = 2.f * s - Xs[(row + 8) * C + c];
        size_t o = (size_t)(r0 + row) * C + c;
        t1b[o] = T1s[(row + 4) * C + c];
        t2b[o] = t2v;
    }
}

// ---------------------------------------------------------------------------
// Pack all W matrices -> mma B fragments, one launch.
// ---------------------------------------------------------------------------
__device__ __forceinline__ uint32_t pack_bf16x2(float a, float b) {
    __nv_bfloat162 h = __floats2bfloat162_rn(a, b);
    return *(uint32_t*)&h;
}
__device__ void pack_one(const float* __restrict__ W, int KREAL, int e,
                         uint4* __restrict__ dst)
{
    int l = e & 31, j = (e >> 5) & 7, s = e >> 8;
    int n = j * 8 + (l >> 2);
    int k0 = s * 16 + (l & 3) * 2;
    float w[4];
#pragma unroll
    for (int i = 0; i < 4; i++) {
        int k = k0 + (i >> 1) * 8 + (i & 1);
        w[i] = (k < KREAL) ? W[(size_t)k * 64 + n] : 0.f;
    }
    float h[4], lo[4];
#pragma unroll
    for (int i = 0; i < 4; i++) {
        __nv_bfloat16 hb = __float2bfloat16_rn(w[i]);
        h[i] = __bfloat162float(hb);
        lo[i] = w[i] - h[i];
    }
    dst[e] = make_uint4(pack_bf16x2(h[0], h[1]), pack_bf16x2(h[2], h[3]),
                        pack_bf16x2(lo[0], lo[1]), pack_bf16x2(lo[2], lo[3]));
}
__global__ void pack_all(const float* __restrict__ W1, const float* __restrict__ W2,
                         const float* __restrict__ W3, const float* __restrict__ W4,
                         uint4* __restrict__ wf)
{
    int e = blockIdx.x * blockDim.x + threadIdx.x;
    if (e < 512) { pack_one(W1, 24, e, wf); return; }
    e -= 512;
    if (e < 3072) { pack_one(W2, 192, e, wf + 3072); return; }
    e -= 3072;
    if (e < 3072) { pack_one(W3, 192, e, wf + 2 * 3072); return; }
    e -= 3072;
    if (e < 3072) { pack_one(W4, 192, e, wf + 3 * 3072); return; }
}

// ---------------------------------------------------------------------------
// mma helpers
// ---------------------------------------------------------------------------
__device__ __forceinline__ void mma_bf16(float* c, const uint32_t* a,
                                         uint32_t b0, uint32_t b1) {
    asm volatile(
        "mma.sync.aligned.m16n8k16.row.col.f32.bf16.bf16.f32 "
        "{%0,%1,%2,%3}, {%4,%5,%6,%7}, {%8,%9}, {%0,%1,%2,%3};"
        : "+f"(c[0]), "+f"(c[1]), "+f"(c[2]), "+f"(c[3])
        : "r"(a[0]), "r"(a[1]), "r"(a[2]), "r"(a[3]), "r"(b0), "r"(b1));
}
__device__ __forceinline__ void cvt_hilo(float2 v, uint32_t& hi, uint32_t& lo) {
    __nv_bfloat162 h = __floats2bfloat162_rn(v.x, v.y);
    float2 hf = __bfloat1622float2(h);
    __nv_bfloat162 l = __floats2bfloat162_rn(v.x - hf.x, v.y - hf.y);
    hi = *(uint32_t*)&h;
    lo = *(uint32_t*)&l;
}
// 9-tap dot for 4 channels at once.
__device__ __forceinline__ float4 vdot9x4(const float* __restrict__ vp,
                                          const float4* __restrict__ win)
{
    float4 vA = *(const float4*)vp;
    float4 vB = *(const float4*)(vp + 4);
    float  vC = vp[8];
    float v[9] = {vA.x, vA.y, vA.z, vA.w, vB.x, vB.y, vB.z, vB.w, vC};
    float4 s = make_float4(0.f, 0.f, 0.f, 0.f);
#pragma unroll
    for (int j = 0; j < 9; j++) {
        s.x += v[j] * win[j].x;
        s.y += v[j] * win[j].y;
        s.z += v[j] * win[j].z;
        s.w += v[j] * win[j].w;
    }
    return s;
}

// ---------------------------------------------------------------------------
// Layer-1 GEMM (Fin=8) from gmem (x, t1, t2).
// ---------------------------------------------------------------------------
__device__ __forceinline__ float2 loadA8(const float* __restrict__ s0,
                                         const float* __restrict__ s1,
                                         const float* __restrict__ s2,
                                         size_t row, int k) {
    if (k >= 24) return make_float2(0.f, 0.f);
    const float* sp = (k < 8) ? s0 : (k < 16) ? s1 : s2;
    return *(const float2*)(sp + row * 8 + (k & 7));
}

__global__ __launch_bounds__(256) void mma_gemm8(
    const float* __restrict__ s0, const float* __restrict__ s1,
    const float* __restrict__ s2, const uint4* __restrict__ wf,
    const float* __restrict__ bias, float* __restrict__ out)
{
    const int t = threadIdx.x, warp = t >> 5, l = t & 31;
    const int qr = l >> 2, qc = (l & 3) * 2;
    const size_t mb = (size_t)blockIdx.x * 128 + warp * 16;

    float acc[8][4];
#pragma unroll
    for (int j = 0; j < 8; j++)
#pragma unroll
        for (int i = 0; i < 4; i++) acc[j][i] = 0.f;

#pragma unroll
    for (int s = 0; s < 2; s++) {
        const int k0 = s * 16 + qc;
        float2 v00 = loadA8(s0, s1, s2, mb + qr,     k0);
        float2 v10 = loadA8(s0, s1, s2, mb + qr + 8, k0);
        float2 v01 = loadA8(s0, s1, s2, mb + qr,     k0 + 8);
        float2 v11 = loadA8(s0, s1, s2, mb + qr + 8, k0 + 8);
        uint32_t ahi[4], alo[4];
        cvt_hilo(v00, ahi[0], alo[0]);
        cvt_hilo(v10, ahi[1], alo[1]);
        cvt_hilo(v01, ahi[2], alo[2]);
        cvt_hilo(v11, ahi[3], alo[3]);
#pragma unroll
        for (int j = 0; j < 8; j++) {
            uint4 bfr = __ldg(&wf[(s * 8 + j) * 32 + l]);
            mma_bf16(acc[j], ahi, bfr.x, bfr.y);
            mma_bf16(acc[j], ahi, bfr.z, bfr.w);
            mma_bf16(acc[j], alo, bfr.x, bfr.y);
        }
    }

#pragma unroll
    for (int j = 0; j < 8; j++) {
        const int n = j * 8 + qc;
        float b0 = __ldg(bias + n), b1 = __ldg(bias + n + 1);
        float z[4] = {acc[j][0] + b0, acc[j][1] + b1, acc[j][2] + b0, acc[j][3] + b1};
#pragma unroll
        for (int i = 0; i < 4; i++) z[i] = (z[i] > 0.f) ? z[i] : expm1f(z[i]);
        *(float2*)(out + (mb + qr) * 64 + n)     = make_float2(z[0], z[1]);
        *(float2*)(out + (mb + qr + 8) * 64 + n) = make_float2(z[2], z[3]);
    }
}

// ---------------------------------------------------------------------------
// Fused mid layer v6: float4-vectorized stencil (stride-66 planes, float2
// T1 accesses) + mma GEMM. 76224 B smem -> 3 CTAs/SM.
// ---------------------------------------------------------------------------
#define SPT 66
#define T1R 136
#define T2R 128
#define OFF_T1 0
#define OFF_T2 (T1R * SPT)                   // 8976
#define OFF_V  (OFF_T2 + T2R * SPT)          // 17424 (16B aligned)
#define SM_FLOATS (OFF_V + T1R * 12)         // 19056
#define SM_MID (SM_FLOATS * 4)               // 76224 B -> 3 CTAs/SM
#define OFF_W  SM_FLOATS
#define SM_OUT ((SM_FLOATS + 384) * 4)

__device__ __forceinline__ float4 ld_t1(const float* __restrict__ sm, int row, int c4) {
    float2 a = *(const float2*)&sm[OFF_T1 + row * SPT + c4];
    float2 b = *(const float2*)&sm[OFF_T1 + row * SPT + c4 + 2];
    return make_float4(a.x, a.y, b.x, b.y);
}

__device__ __forceinline__ void fused_stencil_v6(
    float* __restrict__ sm, const float* __restrict__ x,
    const float* __restrict__ vals, int b, int r0, int t)
{
    const int c4  = (t & 15) * 4;   // first of 4 owned channels
    const int grp = t >> 4;         // 0..15

    // vals rows [r0-4, r0+132) -> V plane stride 12
    for (int idx = t; idx < T1R * DEG; idx += 256) {
        int row = idx / DEG, j = idx % DEG;
        int gr = (r0 - 4 + row + NN) & NMASK;
        sm[OFF_V + row * 12 + j] = vals[(size_t)gr * DEG + j];
    }
    __syncthreads();

    const float4* xb4 = (const float4*)(x + (size_t)b * NN * 64) + (c4 >> 2);

    // Phase 1: T1 local rows [grp*9, grp*9+9) clipped to [0,136).
    {
        const int lr0 = grp * 9;
        float4 xw[9];
#pragma unroll
        for (int j = 0; j < 9; j++) {
            int gr = (r0 - 8 + lr0 + j + NN) & NMASK;
            xw[j] = __ldg(xb4 + (size_t)gr * 16);
        }
#pragma unroll
        for (int i = 0; i < 9; i++) {
            const int lr = lr0 + i;
            if (lr < T1R) {
                float4 s = vdot9x4(&sm[OFF_V + lr * 12], xw);
                *(float2*)&sm[OFF_T1 + lr * SPT + c4]     = make_float2(s.x, s.y);
                *(float2*)&sm[OFF_T1 + lr * SPT + c4 + 2] = make_float2(s.z, s.w);
            }
            if (i < 8) {
                int gr = (r0 - 8 + lr0 + 9 + i + NN) & NMASK;
                float4 xn = __ldg(xb4 + (size_t)gr * 16);
#pragma unroll
                for (int j = 0; j < 8; j++) xw[j] = xw[j + 1];
                xw[8] = xn;
            }
        }
    }
    __syncthreads();

    // Phase 2: T2 rows [grp*8, grp*8+8), sliding T1 window.
    {
        const int row0 = grp * 8;
        float4 w[9];
#pragma unroll
        for (int j = 0; j < 9; j++) w[j] = ld_t1(sm, row0 + j, c4);
#pragma unroll
        for (int i = 0; i < 8; i++) {
            const int row = row0 + i;
            float4 s = vdot9x4(&sm[OFF_V + (row + 4) * 12], w);
            float4 xv = __ldg(xb4 + (size_t)(r0 + row) * 16);
            float4 t2;
            t2.x = 2.f * s.x - xv.x;
            t2.y = 2.f * s.y - xv.y;
            t2.z = 2.f * s.z - xv.z;
            t2.w = 2.f * s.w - xv.w;
            *(float2*)&sm[OFF_T2 + row * SPT + c4]     = make_float2(t2.x, t2.y);
            *(float2*)&sm[OFF_T2 + row * SPT + c4 + 2] = make_float2(t2.z, t2.w);
            if (i < 7) {
#pragma unroll
                for (int j = 0; j < 8; j++) w[j] = w[j + 1];
                w[8] = ld_t1(sm, row + 9, c4);
            }
        }
    }
    __syncthreads();
}

__device__ __forceinline__ float2 loadA_f(const float* __restrict__ sm,
                                          const float* __restrict__ xrow0,
                                          int rl, int k)
{
    if (k < 64)  return *(const float2*)(xrow0 + (size_t)rl * 64 + k);
    if (k < 128) return *(const float2*)(sm + OFF_T1 + (rl + 4) * SPT + (k - 64));
    return *(const float2*)(sm + OFF_T2 + rl * SPT + (k - 128));
}

__global__ __launch_bounds__(256, 3) void fused_mid(
    const float* __restrict__ x, const float* __restrict__ vals,
    const uint4* __restrict__ wf, const float* __restrict__ bias,
    float* __restrict__ out)
{
    extern __shared__ __align__(16) float sm[];
    const int b  = blockIdx.y;
    const int r0 = blockIdx.x * 128;
    const int t  = threadIdx.x;

    fused_stencil_v6(sm, x, vals, b, r0, t);

    const int warp = t >> 5, l = t & 31;
    const int qr = l >> 2, qc = (l & 3) * 2;
    const int rl0 = warp * 16;
    const float* xrow0 = x + ((size_t)b * NN + r0) * 64;

    float acc[8][4];
#pragma unroll
    for (int j = 0; j < 8; j++)
#pragma unroll
        for (int i = 0; i < 4; i++) acc[j][i] = 0.f;

#pragma unroll
    for (int s = 0; s < 12; s++) {
        const int k0 = s * 16 + qc;
        float2 v00 = loadA_f(sm, xrow0, rl0 + qr,     k0);
        float2 v10 = loadA_f(sm, xrow0, rl0 + qr + 8, k0);
        float2 v01 = loadA_f(sm, xrow0, rl0 + qr,     k0 + 8);
        float2 v11 = loadA_f(sm, xrow0, rl0 + qr + 8, k0 + 8);
        uint32_t ahi[4], alo[4];
        cvt_hilo(v00, ahi[0], alo[0]);
        cvt_hilo(v10, ahi[1], alo[1]);
        cvt_hilo(v01, ahi[2], alo[2]);
        cvt_hilo(v11, ahi[3], alo[3]);
#pragma unroll
        for (int j = 0; j < 8; j++) {
            uint4 bfr = __ldg(&wf[(s * 8 + j) * 32 + l]);
            mma_bf16(acc[j], ahi, bfr.x, bfr.y);
            mma_bf16(acc[j], ahi, bfr.z, bfr.w);
            mma_bf16(acc[j], alo, bfr.x, bfr.y);
        }
    }

    const size_t mb = (size_t)b * NN + r0 + rl0;
#pragma unroll
    for (int j = 0; j < 8; j++) {
        const int n = j * 8 + qc;
        float b0 = __ldg(bias + n), b1 = __ldg(bias + n + 1);
        float z[4] = {acc[j][0] + b0, acc[j][1] + b1, acc[j][2] + b0, acc[j][3] + b1};
#pragma unroll
        for (int i = 0; i < 4; i++) z[i] = (z[i] > 0.f) ? z[i] : expm1f(z[i]);
        *(float2*)(out + (mb + qr) * 64 + n)     = make_float2(z[0], z[1]);
        *(float2*)(out + (mb + qr + 8) * 64 + n) = make_float2(z[2], z[3]);
    }
}

// ---------------------------------------------------------------------------
// Fused final layer: vectorized stencil + 192x2 projection (no ELU).
// ---------------------------------------------------------------------------
__global__ __launch_bounds__(256, 3) void fused_out(
    const float* __restrict__ x, const float* __restrict__ vals,
    const float* __restrict__ W, const float* __restrict__ bias,
    float* __restrict__ out)
{
    extern __shared__ __align__(16) float sm[];
    const int b  = blockIdx.y;
    const int r0 = blockIdx.x * 128;
    const int t  = threadIdx.x;

    for (int idx = t; idx < 384; idx += 256) sm[OFF_W + idx] = W[idx];
    fused_stencil_v6(sm, x, vals, b, r0, t);

    if ((t & 1) == 0) {
        const int row = t >> 1;
        const float* xr = x + ((size_t)b * NN + r0 + row) * 64;
        float a0 = bias[0], a1 = bias[1];
#pragma unroll
        for (int i = 0; i < 32; i++) {
            float2 v = *(const float2*)(xr + i * 2);
            const float* wp = sm + OFF_W + (i * 2) * 2;
            a0 += v.x * wp[0] + v.y * wp[2];
            a1 += v.x * wp[1] + v.y * wp[3];
        }
        {
            const float* base = sm + OFF_T1 + (row + 4) * SPT;
#pragma unroll
            for (int i = 0; i < 32; i++) {
                float2 v = *(const float2*)(base + i * 2);
                const float* wp = sm + OFF_W + (64 + i * 2) * 2;
                a0 += v.x * wp[0] + v.y * wp[2];
                a1 += v.x * wp[1] + v.y * wp[3];
            }
        }
        {
            const float* base = sm + OFF_T2 + row * SPT;
#pragma unroll
            for (int i = 0; i < 32; i++) {
                float2 v = *(const float2*)(base + i * 2);
                const float* wp = sm + OFF_W + (128 + i * 2) * 2;
                a0 += v.x * wp[0] + v.y * wp[2];
                a1 += v.x * wp[1] + v.y * wp[3];
            }
        }
        *(float2*)&out[((size_t)b * NN + r0 + row) * 2] = make_float2(a0, a1);
    }
}

// ---------------------------------------------------------------------------
extern "C" void kernel_launch(void* const* d_in, const int* in_sizes, int n_in,
                              void* d_out, int out_size)
{
    const float* x    = (const float*)d_in[0];
    const float* vals = (const float*)d_in[3];
    const float* W1 = (const float*)d_in[4];  const float* b1 = (const float*)d_in[5];
    const float* W2 = (const float*)d_in[6];  const float* b2 = (const float*)d_in[7];
    const float* W3 = (const float*)d_in[8];  const float* b3 = (const float*)d_in[9];
    const float* W4 = (const float*)d_in[10]; const float* b4 = (const float*)d_in[11];
    const float* W5 = (const float*)d_in[12]; const float* b5 = (const float*)d_in[13];

    float *bufA, *bufB, *t1, *t2;
    uint4* wf;
    cudaGetSymbolAddress((void**)&bufA, g_bufA);
    cudaGetSymbolAddress((void**)&bufB, g_bufB);
    cudaGetSymbolAddress((void**)&t1,   g_t1s);
    cudaGetSymbolAddress((void**)&t2,   g_t2s);
    cudaGetSymbolAddress((void**)&wf,   g_wfrag);

    cudaFuncSetAttribute(fused_mid, cudaFuncAttributeMaxDynamicSharedMemorySize, SM_MID);
    cudaFuncSetAttribute(fused_out, cudaFuncAttributeMaxDynamicSharedMemorySize, SM_OUT);

    pack_all<<<38, 256>>>(W1, W2, W3, W4, wf);

    const int M = BB * NN;
    dim3 gS8(NN / 256, BB);
    dim3 gF(NN / 128, BB);
    const int gG = M / 128;

    // Layer 1: Fin=8 -> 64
    stencil_kernel<8, 256><<<gS8, 256>>>(x, vals, t1, t2);
    mma_gemm8<<<gG, 256>>>(x, t1, t2, wf, b1, bufA);

    // Layers 2-4: fused vectorized stencil + GEMM (3 CTAs/SM)
    fused_mid<<<gF, 256, SM_MID>>>(bufA, vals, wf + 3072, b2, bufB);
    fused_mid<<<gF, 256, SM_MID>>>(bufB, vals, wf + 2 * 3072, b3, bufA);
    fused_mid<<<gF, 256, SM_MID>>>(bufA, vals, wf + 3 * 3072, b4, bufB);

    // Layer 5: fused stencil + 192x2 projection
    fused_out<<<gF, 256, SM_OUT>>>(bufB, vals, W5, b5, (float*)d_out);
}